// round 3
// baseline (speedup 1.0000x reference)
#include <cuda_runtime.h>
#include <math.h>

// ---- problem constants ----
#define NFFT      512
#define HOP       256
#define NBIN      19      // rfft bins 13..31  (400 <= f < 1000 Hz, df = 31.25)
#define BIN0      13
#define NANG      18001
#define MICS      4
#define NFRM      4       // EST_NUM frames, t = 120..123
#define SAMPLE_OFF 30464  // first sample used = 119*256
#define NSMP      1280    // samples 30464..31743

// per-frequency reduced projector coefficients:
// [q0, q1r, q1i, q2r, q2i, q3r, q3i, pad]
__device__ float g_Q[NBIN * 8];

// ============================================================
// Kernel 1 (1 block, 512 threads):
//   windowed DFT of 4 frames x 4 mics x 19 bins  ->
//   4x4 complex covariance per bin -> complex Jacobi eigen (double) ->
//   noise projector P = En En^H -> diagonal-sum coefficients Q_m
// ============================================================
__global__ void __launch_bounds__(512, 1) k_cov_eig(const float* __restrict__ x)
{
    __shared__ float  s_buf[NSMP * MICS];   // 20 KB: contiguous samples, mic-interleaved
    __shared__ float  s_cos[NFFT];
    __shared__ float  s_sin[NFFT];
    __shared__ float  s_win[NFFT];
    __shared__ float2 s_X[NFRM][MICS][NBIN];

    const int tid = threadIdx.x;

    // load the only samples the algorithm actually uses (coalesced, 20 KB)
    const float* src = x + (size_t)SAMPLE_OFF * MICS;
    for (int i = tid; i < NSMP * MICS; i += blockDim.x) s_buf[i] = src[i];

    // twiddle + window tables (double-evaluated, float-stored)
    if (tid < NFFT) {
        double a = (double)tid * (M_PI / 256.0);   // 2*pi*n/512
        s_cos[tid] = (float)cos(a);
        s_sin[tid] = (float)sin(a);
        // sqrt(0.5*(1-cos(2*pi*n/512))) == sin(pi*n/512) for n in [0,512)
        s_win[tid] = (float)sin((double)tid * (M_PI / 512.0));
    }
    __syncthreads();

    // ---- DFT: one thread per (frame t, mic c, bin k) = 304 threads ----
    if (tid < NFRM * MICS * NBIN) {
        int t   = tid / (MICS * NBIN);
        int rem = tid % (MICS * NBIN);
        int c   = rem / NBIN;
        int k   = rem % NBIN;
        int bin = k + BIN0;
        int base = t * HOP;                 // frame (120+t) starts at buf sample t*256
        float re = 0.f, im = 0.f;
        int idx = 0;                        // (bin*n) mod 512, exact integer phase
        #pragma unroll 8
        for (int n = 0; n < NFFT; n++) {
            float v = s_buf[(base + n) * MICS + c] * s_win[n];
            re = fmaf(v,  s_cos[idx], re);
            im = fmaf(-v, s_sin[idx], im);
            idx = (idx + bin) & (NFFT - 1);
        }
        s_X[t][c][k] = make_float2(re, im);
    }
    __syncthreads();

    // ---- eigen + projector: one thread per frequency bin ----
    if (tid < NBIN) {
        const int f = tid;
        double Ar[4][4], Ai[4][4], Vr[4][4], Vi[4][4];

        // covariance  A[c][d] = (1/4) sum_t X[t][c] * conj(X[t][d])
        for (int c = 0; c < 4; c++)
            for (int d = 0; d < 4; d++) {
                double sr = 0.0, si = 0.0;
                #pragma unroll
                for (int t = 0; t < NFRM; t++) {
                    float2 a = s_X[t][c][f];
                    float2 b = s_X[t][d][f];
                    sr += (double)a.x * b.x + (double)a.y * b.y;
                    si += (double)a.y * b.x - (double)a.x * b.y;
                }
                Ar[c][d] = 0.25 * sr;
                Ai[c][d] = 0.25 * si;
                Vr[c][d] = (c == d) ? 1.0 : 0.0;
                Vi[c][d] = 0.0;
            }

        double trace = Ar[0][0] + Ar[1][1] + Ar[2][2] + Ar[3][3];
        double thr   = trace * trace * 1e-28 + 1e-300;

        // cyclic complex Jacobi, 10 sweeps
        const int PP[6] = {0,0,0,1,1,2};
        const int QQ[6] = {1,2,3,2,3,3};
        for (int sweep = 0; sweep < 10; sweep++) {
            for (int r = 0; r < 6; r++) {
                int p = PP[r], q = QQ[r];
                double gr = Ar[p][q], gi = Ai[p][q];
                double g2 = gr*gr + gi*gi;
                if (g2 < thr) continue;
                double g  = sqrt(g2);
                double er = gr / g, ei = gi / g;              // e^{i*phi}
                double tau = (Ar[q][q] - Ar[p][p]) / (2.0 * g);
                double tt  = ((tau >= 0.0) ? -1.0 : 1.0) /
                             (fabs(tau) + sqrt(1.0 + tau*tau));
                double cc  = 1.0 / sqrt(1.0 + tt*tt);
                double ss  = tt * cc;
                // R = [[c, -s],[s e^{-i phi}, c e^{-i phi}]]
                double se_r = ss * er, se_i = ss * ei;        // s e^{i phi}
                double ce_r = cc * er, ce_i = cc * ei;        // c e^{i phi}

                // A <- A R   (columns p,q), using conj-phase entries
                for (int i = 0; i < 4; i++) {
                    double pr = Ar[i][p], pi = Ai[i][p];
                    double qr = Ar[i][q], qi = Ai[i][q];
                    // s e^{-i phi} = (se_r, -se_i), c e^{-i phi} = (ce_r, -ce_i)
                    Ar[i][p] =  pr*cc + qr*se_r + qi*se_i;
                    Ai[i][p] =  pi*cc - qr*se_i + qi*se_r;
                    Ar[i][q] = -pr*ss + qr*ce_r + qi*ce_i;
                    Ai[i][q] = -pi*ss - qr*ce_i + qi*ce_r;
                }
                // A <- R^H A   (rows p,q)
                for (int j = 0; j < 4; j++) {
                    double pr = Ar[p][j], pi = Ai[p][j];
                    double qr = Ar[q][j], qi = Ai[q][j];
                    // conj(R[q][p]) = s e^{i phi}, conj(R[q][q]) = c e^{i phi}
                    Ar[p][j] =  cc*pr + se_r*qr - se_i*qi;
                    Ai[p][j] =  cc*pi + se_r*qi + se_i*qr;
                    Ar[q][j] = -ss*pr + ce_r*qr - ce_i*qi;
                    Ai[q][j] = -ss*pi + ce_r*qi + ce_i*qr;
                }
                // V <- V R
                for (int i = 0; i < 4; i++) {
                    double pr = Vr[i][p], pi = Vi[i][p];
                    double qr = Vr[i][q], qi = Vi[i][q];
                    Vr[i][p] =  pr*cc + qr*se_r + qi*se_i;
                    Vi[i][p] =  pi*cc - qr*se_i + qi*se_r;
                    Vr[i][q] = -pr*ss + qr*ce_r + qi*ce_i;
                    Vi[i][q] = -pi*ss - qr*ce_i + qi*ce_r;
                }
            }
        }

        // two smallest eigenvalues -> noise subspace
        double ev[4] = {Ar[0][0], Ar[1][1], Ar[2][2], Ar[3][3]};
        int i1 = 0;
        for (int i = 1; i < 4; i++) if (ev[i] < ev[i1]) i1 = i;
        int i2 = (i1 == 0) ? 1 : 0;
        for (int i = 0; i < 4; i++) if (i != i1 && ev[i] < ev[i2]) i2 = i;

        // P = v1 v1^H + v2 v2^H  (only diagonal sums Q_m needed)
        double Pr[4][4], Pi[4][4];
        for (int c = 0; c < 4; c++)
            for (int d = 0; d < 4; d++) {
                double sr = Vr[c][i1]*Vr[d][i1] + Vi[c][i1]*Vi[d][i1]
                          + Vr[c][i2]*Vr[d][i2] + Vi[c][i2]*Vi[d][i2];
                double si = Vi[c][i1]*Vr[d][i1] - Vr[c][i1]*Vi[d][i1]
                          + Vi[c][i2]*Vr[d][i2] - Vr[c][i2]*Vi[d][i2];
                Pr[c][d] = sr; Pi[c][d] = si;
            }

        float* q = &g_Q[f * 8];
        q[0] = (float)(Pr[0][0] + Pr[1][1] + Pr[2][2] + Pr[3][3]);
        q[1] = (float)(Pr[1][0] + Pr[2][1] + Pr[3][2]);
        q[2] = (float)(Pi[1][0] + Pi[2][1] + Pi[3][2]);
        q[3] = (float)(Pr[2][0] + Pr[3][1]);
        q[4] = (float)(Pi[2][0] + Pi[3][1]);
        q[5] = (float)(Pr[3][0]);
        q[6] = (float)(Pi[3][0]);
    }
}

// ============================================================
// Kernel 2: angle sweep. 18001 threads, each reduces 19 freqs.
//   denom(phi) = Q0 + 2*sum_m (ReQm cos(m phi) + ImQm sin(m phi)) + eps
// ============================================================
__global__ void k_spec(float* __restrict__ out)
{
    __shared__ float sQ[NBIN * 8];
    for (int i = threadIdx.x; i < NBIN * 8; i += blockDim.x) sQ[i] = g_Q[i];
    __syncthreads();

    int a = blockIdx.x * blockDim.x + threadIdx.x;
    if (a >= NANG) return;

    float th = (-90.0f + 0.01f * (float)a) * 0.017453292519943295f;
    float st = sinf(th);
    const float C0 = (float)(2.0 * M_PI * 0.1 / 343.0);
    float base = C0 * st;

    float acc = 0.0f;
    #pragma unroll
    for (int k = 0; k < NBIN; k++) {
        float fr  = 31.25f * (float)(BIN0 + k);
        float phi = base * fr;
        float s1, c1;
        sincosf(phi, &s1, &c1);
        float c2 = c1*c1 - s1*s1;
        float s2 = 2.0f*c1*s1;
        float c3 = c2*c1 - s2*s1;
        float s3 = s2*c1 + c2*s1;
        const float* q = &sQ[k * 8];
        float denom = q[0]
            + 2.0f * (q[1]*c1 + q[2]*s1 + q[3]*c2 + q[4]*s2 + q[5]*c3 + q[6]*s3)
            + 1e-8f;
        acc += 1.0f / denom;
    }
    out[a] = acc * (1.0f / 19.0f);
}

extern "C" void kernel_launch(void* const* d_in, const int* in_sizes, int n_in,
                              void* d_out, int out_size)
{
    const float* x = (const float*)d_in[0];
    float* out = (float*)d_out;
    k_cov_eig<<<1, 512>>>(x);
    k_spec<<<(NANG + 255) / 256, 256>>>(out);
}

// round 4
// speedup vs baseline: 7.2897x; 7.2897x over previous
#include <cuda_runtime.h>
#include <math.h>

// ---- problem constants ----
#define NFFT      512
#define HOP       256
#define NBIN      19      // rfft bins 13..31  (400 <= f < 1000 Hz, df = 31.25)
#define BIN0      13
#define NANG      18001
#define MICS      4
#define NFRM      4       // EST_NUM frames, t = 120..123
#define SAMPLE_OFF 30464  // first sample used = 119*256
#define NSMP      1280    // samples 30464..31743

// per-frequency reduced projector coefficients:
// [q0, q1r, q1i, q2r, q2i, q3r, q3i, pad]
__device__ float g_Q[NBIN * 8];

// ============================================================
// Kernel 1 (1 block, 512 threads) — ALL FP32:
//   windowed DFT of 4 frames x 4 mics x 19 bins  ->
//   4x4 complex covariance per bin -> complex Jacobi eigen (float, 6 sweeps)
//   -> noise projector P = En En^H -> diagonal-sum coefficients Q_m
// ============================================================
__global__ void __launch_bounds__(512, 1) k_cov_eig(const float* __restrict__ x)
{
    __shared__ float  s_buf[NSMP * MICS];   // 20 KB
    __shared__ float  s_cos[NFFT];
    __shared__ float  s_sin[NFFT];
    __shared__ float  s_win[NFFT];
    __shared__ float2 s_X[NFRM][MICS][NBIN];

    const int tid = threadIdx.x;

    // load the only samples the algorithm actually uses (coalesced, 20 KB)
    const float* src = x + (size_t)SAMPLE_OFF * MICS;
    for (int i = tid; i < NSMP * MICS; i += blockDim.x) s_buf[i] = src[i];

    // twiddle + window tables (float)
    if (tid < NFFT) {
        float a = (float)tid * (float)(M_PI / 256.0);   // 2*pi*n/512
        float s, c;
        sincosf(a, &s, &c);
        s_cos[tid] = c;
        s_sin[tid] = s;
        // sqrt(0.5*(1-cos(2*pi*n/512))) == sin(pi*n/512) for n in [0,512)
        s_win[tid] = sinf((float)tid * (float)(M_PI / 512.0));
    }
    __syncthreads();

    // ---- DFT: one thread per (frame t, mic c, bin k) = 304 threads ----
    if (tid < NFRM * MICS * NBIN) {
        int t   = tid / (MICS * NBIN);
        int rem = tid % (MICS * NBIN);
        int c   = rem / NBIN;
        int k   = rem % NBIN;
        int bin = k + BIN0;
        int base = t * HOP;                 // frame (120+t) starts at buf sample t*256
        float re = 0.f, im = 0.f;
        int idx = 0;                        // (bin*n) mod 512, exact integer phase
        #pragma unroll 8
        for (int n = 0; n < NFFT; n++) {
            float v = s_buf[(base + n) * MICS + c] * s_win[n];
            re = fmaf(v,  s_cos[idx], re);
            im = fmaf(-v, s_sin[idx], im);
            idx = (idx + bin) & (NFFT - 1);
        }
        s_X[t][c][k] = make_float2(re, im);
    }
    __syncthreads();

    // ---- eigen + projector: one thread per frequency bin ----
    if (tid < NBIN) {
        const int f = tid;
        float Ar[4][4], Ai[4][4], Vr[4][4], Vi[4][4];

        // covariance  A[c][d] = (1/4) sum_t X[t][c] * conj(X[t][d])
        for (int c = 0; c < 4; c++)
            for (int d = 0; d < 4; d++) {
                float sr = 0.f, si = 0.f;
                #pragma unroll
                for (int t = 0; t < NFRM; t++) {
                    float2 a = s_X[t][c][f];
                    float2 b = s_X[t][d][f];
                    sr = fmaf(a.x, b.x, fmaf(a.y, b.y, sr));
                    si = fmaf(a.y, b.x, fmaf(-a.x, b.y, si));
                }
                Ar[c][d] = 0.25f * sr;
                Ai[c][d] = 0.25f * si;
                Vr[c][d] = (c == d) ? 1.0f : 0.0f;
                Vi[c][d] = 0.0f;
            }

        float trace = Ar[0][0] + Ar[1][1] + Ar[2][2] + Ar[3][3];
        float thr   = trace * trace * 1e-14f + 1e-30f;

        // cyclic complex Jacobi, 6 sweeps (quadratic convergence: plenty for fp32)
        const int PP[6] = {0,0,0,1,1,2};
        const int QQ[6] = {1,2,3,2,3,3};
        for (int sweep = 0; sweep < 6; sweep++) {
            for (int r = 0; r < 6; r++) {
                int p = PP[r], q = QQ[r];
                float gr = Ar[p][q], gi = Ai[p][q];
                float g2 = gr*gr + gi*gi;
                if (g2 < thr) continue;
                float g  = sqrtf(g2);
                float inv_g = 1.0f / g;
                float er = gr * inv_g, ei = gi * inv_g;       // e^{i*phi}
                float tau = (Ar[q][q] - Ar[p][p]) * (0.5f * inv_g);
                float tt  = ((tau >= 0.0f) ? -1.0f : 1.0f) /
                            (fabsf(tau) + sqrtf(1.0f + tau*tau));
                float cc  = rsqrtf(1.0f + tt*tt);
                float ss  = tt * cc;
                // R = [[c, -s],[s e^{-i phi}, c e^{-i phi}]]
                float se_r = ss * er, se_i = ss * ei;         // s e^{i phi}
                float ce_r = cc * er, ce_i = cc * ei;         // c e^{i phi}

                // A <- A R   (columns p,q)
                #pragma unroll
                for (int i = 0; i < 4; i++) {
                    float pr = Ar[i][p], pi = Ai[i][p];
                    float qr = Ar[i][q], qi = Ai[i][q];
                    Ar[i][p] =  pr*cc + qr*se_r + qi*se_i;
                    Ai[i][p] =  pi*cc - qr*se_i + qi*se_r;
                    Ar[i][q] = -pr*ss + qr*ce_r + qi*ce_i;
                    Ai[i][q] = -pi*ss - qr*ce_i + qi*ce_r;
                }
                // A <- R^H A   (rows p,q)
                #pragma unroll
                for (int j = 0; j < 4; j++) {
                    float pr = Ar[p][j], pi = Ai[p][j];
                    float qr = Ar[q][j], qi = Ai[q][j];
                    Ar[p][j] =  cc*pr + se_r*qr - se_i*qi;
                    Ai[p][j] =  cc*pi + se_r*qi + se_i*qr;
                    Ar[q][j] = -ss*pr + ce_r*qr - ce_i*qi;
                    Ai[q][j] = -ss*pi + ce_r*qi + ce_i*qr;
                }
                // V <- V R
                #pragma unroll
                for (int i = 0; i < 4; i++) {
                    float pr = Vr[i][p], pi = Vi[i][p];
                    float qr = Vr[i][q], qi = Vi[i][q];
                    Vr[i][p] =  pr*cc + qr*se_r + qi*se_i;
                    Vi[i][p] =  pi*cc - qr*se_i + qi*se_r;
                    Vr[i][q] = -pr*ss + qr*ce_r + qi*ce_i;
                    Vi[i][q] = -pi*ss - qr*ce_i + qi*ce_r;
                }
            }
        }

        // two smallest eigenvalues -> noise subspace
        float ev[4] = {Ar[0][0], Ar[1][1], Ar[2][2], Ar[3][3]};
        int i1 = 0;
        for (int i = 1; i < 4; i++) if (ev[i] < ev[i1]) i1 = i;
        int i2 = (i1 == 0) ? 1 : 0;
        for (int i = 0; i < 4; i++) if (i != i1 && ev[i] < ev[i2]) i2 = i;

        // P = v1 v1^H + v2 v2^H  (only diagonal sums Q_m needed)
        float Pr[4][4], Pi[4][4];
        #pragma unroll
        for (int c = 0; c < 4; c++)
            #pragma unroll
            for (int d = 0; d <= c; d++) {
                float sr = Vr[c][i1]*Vr[d][i1] + Vi[c][i1]*Vi[d][i1]
                         + Vr[c][i2]*Vr[d][i2] + Vi[c][i2]*Vi[d][i2];
                float si = Vi[c][i1]*Vr[d][i1] - Vr[c][i1]*Vi[d][i1]
                         + Vi[c][i2]*Vr[d][i2] - Vr[c][i2]*Vi[d][i2];
                Pr[c][d] = sr; Pi[c][d] = si;
            }

        float* q = &g_Q[f * 8];
        q[0] = Pr[0][0] + Pr[1][1] + Pr[2][2] + Pr[3][3];
        q[1] = Pr[1][0] + Pr[2][1] + Pr[3][2];
        q[2] = Pi[1][0] + Pi[2][1] + Pi[3][2];
        q[3] = Pr[2][0] + Pr[3][1];
        q[4] = Pi[2][0] + Pi[3][1];
        q[5] = Pr[3][0];
        q[6] = Pi[3][0];
    }
}

// ============================================================
// Kernel 2: angle sweep. 18001 threads, each reduces 19 freqs.
//   denom(phi) = Q0 + 2*sum_m (ReQm cos(m phi) + ImQm sin(m phi)) + eps
// Bins are uniformly spaced in phi -> angle-addition recurrence:
// only 2 sincosf per thread instead of 19.
// ============================================================
__global__ void k_spec(float* __restrict__ out)
{
    __shared__ float sQ[NBIN * 8];
    for (int i = threadIdx.x; i < NBIN * 8; i += blockDim.x) sQ[i] = g_Q[i];
    __syncthreads();

    int a = blockIdx.x * blockDim.x + threadIdx.x;
    if (a >= NANG) return;

    float th = (-90.0f + 0.01f * (float)a) * 0.017453292519943295f;
    float st = sinf(th);
    const float C0 = (float)(2.0 * M_PI * 0.1 / 343.0);
    float base = C0 * st;

    // phi_k = base * 31.25 * (BIN0 + k)
    float dphi = base * 31.25f;
    float phi0 = dphi * (float)BIN0;
    float s1, c1, sd, cd;
    sincosf(phi0, &s1, &c1);
    sincosf(dphi, &sd, &cd);

    float acc = 0.0f;
    #pragma unroll
    for (int k = 0; k < NBIN; k++) {
        float c2 = fmaf(c1, c1, -s1*s1);       // cos 2phi
        float s2 = 2.0f * c1 * s1;             // sin 2phi
        float c3 = fmaf(c2, c1, -s2*s1);       // cos 3phi
        float s3 = fmaf(s2, c1,  c2*s1);       // sin 3phi
        const float* q = &sQ[k * 8];
        float denom = fmaf(2.0f,
              fmaf(q[1], c1, fmaf(q[2], s1,
              fmaf(q[3], c2, fmaf(q[4], s2,
              fmaf(q[5], c3,       q[6]*s3))))),
              q[0]) + 1e-8f;
        acc += 1.0f / denom;
        // advance phi by dphi
        float c1n = fmaf(c1, cd, -s1*sd);
        float s1n = fmaf(s1, cd,  c1*sd);
        c1 = c1n; s1 = s1n;
    }
    out[a] = acc * (1.0f / 19.0f);
}

extern "C" void kernel_launch(void* const* d_in, const int* in_sizes, int n_in,
                              void* d_out, int out_size)
{
    const float* x = (const float*)d_in[0];
    float* out = (float*)d_out;
    k_cov_eig<<<1, 512>>>(x);
    k_spec<<<(NANG + 127) / 128, 128>>>(out);
}

// round 6
// speedup vs baseline: 16.5371x; 2.2686x over previous
#include <cuda_runtime.h>
#include <math.h>

// ---- problem constants ----
#define NFFT      512
#define HOP       256
#define NBIN      19      // rfft bins 13..31  (400 <= f < 1000 Hz, df = 31.25)
#define BIN0      13
#define NANG      18001
#define MICS      4
#define NFRM      4       // EST_NUM frames, t = 120..123
#define SAMPLE_OFF 30464  // first sample used = 119*256
#define NTCK      (NFRM * MICS * NBIN)   // 304 (t,c,k) tuples

// DFT results X[t][c][k], layout (t*MICS+c)*NBIN + k
__device__ float2 gX[NTCK];

// ============================================================
// Kernel 1: warp-parallel windowed DFT. One warp per (t,c,bin).
// 38 blocks x 256 threads = 304 warps. Lane l handles taps l+32j.
// Twiddles: exact integer phase init + unit-rotation recurrence.
// ============================================================
__global__ void __launch_bounds__(256, 1) k_dft(const float* __restrict__ x)
{
    const int w = (blockIdx.x * 256 + threadIdx.x) >> 5;   // 0..303 exactly
    const int l = threadIdx.x & 31;

    const int t   = w / (MICS * NBIN);
    const int rem = w % (MICS * NBIN);
    const int c   = rem / NBIN;
    const int bin = (rem % NBIN) + BIN0;

    const float ANG = -0.012271846303085130f;              // -2*pi/512
    // phase of lane's first tap: -2*pi*bin*l/512, reduced exactly mod 2*pi
    float c1, s1, cs, ss;
    __sincosf((float)((bin * l)  & 511) * ANG, &s1, &c1);
    __sincosf((float)((bin * 32) & 511) * ANG, &ss, &cs);  // per-step rotation

    const float* px = x + ((size_t)SAMPLE_OFF + (size_t)t * HOP) * MICS + c;

    float re = 0.f, im = 0.f;
    #pragma unroll
    for (int j = 0; j < 16; j++) {
        int n = l + 32 * j;
        float v = px[n * MICS] * __sinf((float)n * (float)(M_PI / 512.0)); // window
        re = fmaf(v, c1, re);
        im = fmaf(v, s1, im);        // s1 tracks sin(-phi): im = -sum v*sin(phi)
        float cn = fmaf(c1, cs, -s1 * ss);
        float sn = fmaf(s1, cs,  c1 * ss);
        c1 = cn; s1 = sn;
    }
    #pragma unroll
    for (int off = 16; off; off >>= 1) {
        re += __shfl_down_sync(0xffffffffu, re, off);
        im += __shfl_down_sync(0xffffffffu, im, off);
    }
    if (l == 0) gX[w] = make_float2(re, im);
}

// ============================================================
// Kernel 2 (fused): each of 141 blocks redundantly computes the
// 19 4x4 eigen problems (warp 0, MUFU math), then all 128 threads
// evaluate their angle of the MUSIC spectrum.
// ============================================================
__global__ void __launch_bounds__(128, 1) k_eig_spec(float* __restrict__ out)
{
    __shared__ float2 sX[NTCK];
    __shared__ float  sQ[NBIN * 8];   // [q0,q1r,q1i,q2r,q2i,q3r,q3i,pad] per bin

    const int tid = threadIdx.x;
    for (int i = tid; i < NTCK; i += 128) sX[i] = gX[i];
    __syncthreads();

    // ---- cov + Jacobi eigen + projector: lanes 0..18 of warp 0 ----
    if (tid < NBIN) {
        const int f = tid;
        float Ar[4][4], Ai[4][4], Vr[4][4], Vi[4][4];

        // A[c][d] = (1/4) sum_t X[t][c] conj(X[t][d])  (Hermitian fill)
        #pragma unroll
        for (int c = 0; c < 4; c++)
            #pragma unroll
            for (int d = 0; d <= c; d++) {
                float sr = 0.f, si = 0.f;
                #pragma unroll
                for (int t = 0; t < NFRM; t++) {
                    float2 a = sX[(t * MICS + c) * NBIN + f];
                    float2 b = sX[(t * MICS + d) * NBIN + f];
                    sr = fmaf(a.x, b.x, fmaf(a.y, b.y, sr));
                    si = fmaf(a.y, b.x, fmaf(-a.x, b.y, si));
                }
                Ar[c][d] = 0.25f * sr;  Ai[c][d] = 0.25f * si;
                Ar[d][c] = 0.25f * sr;  Ai[d][c] = -0.25f * si;
            }
        #pragma unroll
        for (int c = 0; c < 4; c++) {
            Ai[c][c] = 0.f;
            #pragma unroll
            for (int d = 0; d < 4; d++) { Vr[c][d] = (c == d) ? 1.f : 0.f; Vi[c][d] = 0.f; }
        }

        float trace = Ar[0][0] + Ar[1][1] + Ar[2][2] + Ar[3][3];
        float thr   = trace * trace * 1e-14f + 1e-30f;

        const int PP[6] = {0,0,0,1,1,2};
        const int QQ[6] = {1,2,3,2,3,3};
        for (int sweep = 0; sweep < 5; sweep++) {
            #pragma unroll
            for (int r = 0; r < 6; r++) {
                int p = PP[r], q = QQ[r];
                float gr = Ar[p][q], gi = Ai[p][q];
                float g2 = fmaf(gr, gr, gi * gi);
                if (g2 < thr) continue;
                float inv_g = rsqrtf(g2);                  // MUFU.RSQ
                float er = gr * inv_g, ei = gi * inv_g;    // e^{i*phi}
                float tau = (Ar[q][q] - Ar[p][p]) * (0.5f * inv_g);
                float t2  = fmaf(tau, tau, 1.f);
                float root = t2 * rsqrtf(t2);              // sqrt(1+tau^2)
                float tt  = __fdividef((tau >= 0.f) ? -1.f : 1.f, fabsf(tau) + root);
                float cc  = rsqrtf(fmaf(tt, tt, 1.f));
                float ss  = tt * cc;
                float se_r = ss * er, se_i = ss * ei;      // s e^{i phi}
                float ce_r = cc * er, ce_i = cc * ei;      // c e^{i phi}

                #pragma unroll
                for (int i = 0; i < 4; i++) {              // A <- A R
                    float pr = Ar[i][p], pi = Ai[i][p];
                    float qr = Ar[i][q], qi = Ai[i][q];
                    Ar[i][p] =  pr*cc + qr*se_r + qi*se_i;
                    Ai[i][p] =  pi*cc - qr*se_i + qi*se_r;
                    Ar[i][q] = -pr*ss + qr*ce_r + qi*ce_i;
                    Ai[i][q] = -pi*ss - qr*ce_i + qi*ce_r;
                }
                #pragma unroll
                for (int j = 0; j < 4; j++) {              // A <- R^H A
                    float pr = Ar[p][j], pi = Ai[p][j];
                    float qr = Ar[q][j], qi = Ai[q][j];
                    Ar[p][j] =  cc*pr + se_r*qr - se_i*qi;
                    Ai[p][j] =  cc*pi + se_r*qi + se_i*qr;
                    Ar[q][j] = -ss*pr + ce_r*qr - ce_i*qi;
                    Ai[q][j] = -ss*pi + ce_r*qi + ce_i*qr;
                }
                #pragma unroll
                for (int i = 0; i < 4; i++) {              // V <- V R
                    float pr = Vr[i][p], pi = Vi[i][p];
                    float qr = Vr[i][q], qi = Vi[i][q];
                    Vr[i][p] =  pr*cc + qr*se_r + qi*se_i;
                    Vi[i][p] =  pi*cc - qr*se_i + qi*se_r;
                    Vr[i][q] = -pr*ss + qr*ce_r + qi*ce_i;
                    Vi[i][q] = -pi*ss - qr*ce_i + qi*ce_r;
                }
            }
        }

        // two smallest eigenvalues -> noise subspace
        float ev[4] = {Ar[0][0], Ar[1][1], Ar[2][2], Ar[3][3]};
        int i1 = 0;
        for (int i = 1; i < 4; i++) if (ev[i] < ev[i1]) i1 = i;
        int i2 = (i1 == 0) ? 1 : 0;
        for (int i = 0; i < 4; i++) if (i != i1 && ev[i] < ev[i2]) i2 = i;

        // P = v1 v1^H + v2 v2^H, collapsed to diagonal sums Q_m
        float Pr10, Pi10, Pr21, Pi21, Pr32, Pi32, Pr20, Pi20, Pr31, Pi31, Pr30, Pi30;
        float Pd = 0.f;
        #pragma unroll
        for (int c = 0; c < 4; c++)
            Pd += Vr[c][i1]*Vr[c][i1] + Vi[c][i1]*Vi[c][i1]
                + Vr[c][i2]*Vr[c][i2] + Vi[c][i2]*Vi[c][i2];
        #define PCD(c,d, PR, PI) \
            PR = Vr[c][i1]*Vr[d][i1] + Vi[c][i1]*Vi[d][i1] \
               + Vr[c][i2]*Vr[d][i2] + Vi[c][i2]*Vi[d][i2]; \
            PI = Vi[c][i1]*Vr[d][i1] - Vr[c][i1]*Vi[d][i1] \
               + Vi[c][i2]*Vr[d][i2] - Vr[c][i2]*Vi[d][i2];
        PCD(1,0, Pr10, Pi10); PCD(2,1, Pr21, Pi21); PCD(3,2, Pr32, Pi32);
        PCD(2,0, Pr20, Pi20); PCD(3,1, Pr31, Pi31); PCD(3,0, Pr30, Pi30);
        #undef PCD

        float* qo = &sQ[f * 8];
        qo[0] = Pd;
        qo[1] = Pr10 + Pr21 + Pr32;
        qo[2] = Pi10 + Pi21 + Pi32;
        qo[3] = Pr20 + Pr31;
        qo[4] = Pi20 + Pi31;
        qo[5] = Pr30;
        qo[6] = Pi30;
    }
    __syncthreads();

    // ---- angle sweep ----
    int a = blockIdx.x * 128 + tid;
    if (a >= NANG) return;

    float th = (-90.0f + 0.01f * (float)a) * 0.017453292519943295f;
    float st = __sinf(th);
    float base = (float)(2.0 * M_PI * 0.1 / 343.0) * st;

    float dphi = base * 31.25f;
    float phi0 = dphi * (float)BIN0;
    float s1, c1, sd, cd;
    __sincosf(phi0, &s1, &c1);
    __sincosf(dphi, &sd, &cd);

    float acc = 0.0f;
    #pragma unroll
    for (int k = 0; k < NBIN; k++) {
        float c2 = fmaf(c1, c1, -s1*s1);
        float s2 = 2.0f * c1 * s1;
        float c3 = fmaf(c2, c1, -s2*s1);
        float s3 = fmaf(s2, c1,  c2*s1);
        const float* q = &sQ[k * 8];
        float denom = fmaf(2.0f,
              fmaf(q[1], c1, fmaf(q[2], s1,
              fmaf(q[3], c2, fmaf(q[4], s2,
              fmaf(q[5], c3,       q[6]*s3))))),
              q[0]) + 1e-8f;
        acc += __fdividef(1.0f, denom);
        float c1n = fmaf(c1, cd, -s1*sd);
        float s1n = fmaf(s1, cd,  c1*sd);
        c1 = c1n; s1 = s1n;
    }
    out[a] = acc * (1.0f / 19.0f);
}

extern "C" void kernel_launch(void* const* d_in, const int* in_sizes, int n_in,
                              void* d_out, int out_size)
{
    const float* x = (const float*)d_in[0];
    float* out = (float*)d_out;
    k_dft<<<38, 256>>>(x);
    k_eig_spec<<<(NANG + 127) / 128, 128>>>(out);
}